// round 2
// baseline (speedup 1.0000x reference)
#include <cuda_runtime.h>

// Scratch (allocation-free per harness rules). Zero-initialized at load;
// the last block resets both after use so every graph replay starts clean.
__device__ float        g_acc;
__device__ unsigned int g_count;

__global__ void __launch_bounds__(256)
hcl_fused_kernel(const float* __restrict__ pred,
                 const float* __restrict__ temp,
                 const int*   __restrict__ i_idx,
                 const int*   __restrict__ j_idx,
                 float*       __restrict__ out,
                 long long rows, int num_constraints)
{
    const int i0 = __ldg(i_idx + 0), i1 = __ldg(i_idx + 1),
              i2 = __ldg(i_idx + 2), i3 = __ldg(i_idx + 3);
    const int j0 = __ldg(j_idx + 0), j1 = __ldg(j_idx + 1),
              j2 = __ldg(j_idx + 2), j3 = __ldg(j_idx + 3);

    // Specialized path for the dataset's fixed constraint set:
    // pairs (2,5),(5,6),(6,7),(8,3) -> unique cols {2,3,5,6,7,8}.
    const bool fast = (num_constraints == 4 &&
                       i0 == 2 && i1 == 5 && i2 == 6 && i3 == 8 &&
                       j0 == 5 && j1 == 6 && j2 == 7 && j3 == 3);

    float acc = 0.0f;
    long long tid    = (long long)blockIdx.x * blockDim.x + threadIdx.x;
    long long stride = (long long)gridDim.x * blockDim.x;

    if (fast) {
        for (long long r = tid; r < rows; r += stride) {
            const float* row = pred + r * 14;
            // 56r+8 and 56r+24 are 8B-aligned -> legal LDG.64
            float2 c23 = __ldg(reinterpret_cast<const float2*>(row + 2)); // p2,p3
            float  p5  = __ldg(row + 5);
            float2 c67 = __ldg(reinterpret_cast<const float2*>(row + 6)); // p6,p7
            float  p8  = __ldg(row + 8);

            float d0 = fmaxf(c23.x - p5,    0.0f);  // relu(p2 - p5)
            float d1 = fmaxf(p5    - c67.x, 0.0f);  // relu(p5 - p6)
            float d2 = fmaxf(c67.x - c67.y, 0.0f);  // relu(p6 - p7)
            float d3 = fmaxf(p8    - c23.y, 0.0f);  // relu(p8 - p3)

            acc = fmaf(d0, d0, acc);
            acc = fmaf(d1, d1, acc);
            acc = fmaf(d2, d2, acc);
            acc = fmaf(d3, d3, acc);
        }
    } else {
        for (long long r = tid; r < rows; r += stride) {
            const float* row = pred + r * 14;
            float a0 = __ldg(row + i0), b0 = __ldg(row + j0);
            float a1 = __ldg(row + i1), b1 = __ldg(row + j1);
            float a2 = __ldg(row + i2), b2 = __ldg(row + j2);
            float a3 = __ldg(row + i3), b3 = __ldg(row + j3);
            float d0 = fmaxf(a0 - b0, 0.0f);
            float d1 = fmaxf(a1 - b1, 0.0f);
            float d2 = fmaxf(a2 - b2, 0.0f);
            float d3 = fmaxf(a3 - b3, 0.0f);
            acc = fmaf(d0, d0, acc);
            acc = fmaf(d1, d1, acc);
            acc = fmaf(d2, d2, acc);
            acc = fmaf(d3, d3, acc);
        }
    }

    // Warp reduction
    #pragma unroll
    for (int off = 16; off > 0; off >>= 1)
        acc += __shfl_xor_sync(0xFFFFFFFFu, acc, off);

    // Block reduction -> one global atomic per block
    __shared__ float s_part;
    __shared__ bool  s_last;
    if (threadIdx.x == 0) s_part = 0.0f;
    __syncthreads();
    if ((threadIdx.x & 31) == 0) atomicAdd(&s_part, acc);
    __syncthreads();

    if (threadIdx.x == 0) {
        atomicAdd(&g_acc, s_part);
        __threadfence();
        unsigned t = atomicAdd(&g_count, 1u);
        s_last = (t == (unsigned)gridDim.x - 1u);
    }
    __syncthreads();

    // Last block finalizes: read+reset accumulator atomically, write output,
    // reset the counter. Leaves globals zeroed for the next graph replay.
    if (s_last && threadIdx.x == 0) {
        float total = atomicExch(&g_acc, 0.0f);
        out[0] = total / ((float)rows * temp[0] * (float)num_constraints);
        g_count = 0u;
    }
}

extern "C" void kernel_launch(void* const* d_in, const int* in_sizes, int n_in,
                              void* d_out, int out_size)
{
    const float* pred  = (const float*)d_in[0];
    const float* temp  = (const float*)d_in[1];
    const int*   i_idx = (const int*)d_in[2];
    const int*   j_idx = (const int*)d_in[3];
    float* out = (float*)d_out;

    const int num_classes = 14;                       // fixed problem shape
    const long long rows = (long long)in_sizes[0] / num_classes;
    const int num_constraints = in_sizes[2];          // 4

    const int threads = 256;
    long long want = (rows + threads - 1) / threads;
    int blocks = (int)(want < 2368 ? want : 2368);    // 148 SMs * 16

    hcl_fused_kernel<<<blocks, threads>>>(pred, temp, i_idx, j_idx, out,
                                          rows, num_constraints);
}